// round 13
// baseline (speedup 1.0000x reference)
#include <cuda_runtime.h>
#include <math.h>

#define TOKENS   16384
#define NEXP     256
#define HID      7168
#define NGROUP   8
#define TOPKG    4
#define TOPKN    8

// Scratch logits [T, E] (16 MB).
__device__ float g_logits[TOKENS * NEXP];

// ---------------------------------------------------------------------------
// Kernel 1: fp32 router GEMM, EIGEN-FAITHFUL ASSOCIATION (FROZEN NUMERICS):
//   per output: serial ascending-k fma chain within kc=248 panels,
//   C = ((0+S1)+S2)+... separate rn-adds at panel folds, remainder 224 last.
// Speed shape (R11 structure): BM=BN=128, BK=16, 256 threads, 8x8/thread,
// double-buffered, packed fma.rn.f32x2 over column pairs.
// R13 change: jp-outer/i-inner FMA order -> bq[jp] stable across 8 back-to-
// back FFMA2s in the same operand slot (reuse-cache friendly; targets rt 3->2).
// ---------------------------------------------------------------------------
#define BM 128
#define BN 128
#define BK 16
#define KC  248
#define TPAD 4
#define TROW (BM + TPAD)     // 132 floats; 528B rows (16B aligned)
#define TILE_F (BK * TROW)   // 2112 floats

#define SM_AS    0
#define SM_BS    (2 * TILE_F)
#define SM_TOT   (4 * TILE_F)                     // float offset; *4 % 8 == 0
#define SM_TOTAL ((4 * TILE_F) * 4 + 32 * 256 * 8)  // 33792 + 65536 = 99328 B

#define FMA2(acc, a, b) \
    asm("fma.rn.f32x2 %0, %1, %2, %0;" : "+l"(acc) : "l"(a), "l"(b))
#define ADD2(d, x, y) \
    asm("add.rn.f32x2 %0, %1, %2;" : "=l"(d) : "l"(x), "l"(y))
#define SPLAT2(p, f) \
    asm("mov.b64 %0, {%1, %1};" : "=l"(p) : "f"(f))
#define UNPK2(lo, hi, p) \
    asm("mov.b64 {%0, %1}, %2;" : "=f"(lo), "=f"(hi) : "l"(p))

__global__ __launch_bounds__(256, 2) void router_gemm(
    const float* __restrict__ A,   // [T, H]
    const float* __restrict__ B,   // [E, H]
    float* __restrict__ C,         // [T, E]
    int T, int H, int E)
{
    extern __shared__ float sm[];
    float* sAs = sm + SM_AS;
    float* sBs = sm + SM_BS;
    unsigned long long* sTot = reinterpret_cast<unsigned long long*>(sm + SM_TOT);

    const int tid = threadIdx.x;
    const int tx = tid & 15;
    const int ty = tid >> 4;
    const int tile_m = blockIdx.y * BM;
    const int tile_n = blockIdx.x * BN;

    const int lrow = tid >> 1;
    const int lcol = (tid & 1) * 8;

    const float* Ab = A + (size_t)(tile_m + lrow) * H + lcol;
    const float* Bb = B + (size_t)(tile_n + lrow) * H + lcol;

    #pragma unroll
    for (int i = 0; i < 32; i++) sTot[i * 256 + tid] = 0ull;

    // acc[i][jp]: packed pair = outputs (col 2jp, 2jp+1) for row i
    unsigned long long acc[8][4];
    #pragma unroll
    for (int i = 0; i < 8; i++)
        #pragma unroll
        for (int jp = 0; jp < 4; jp++) acc[i][jp] = 0ull;

    const int NIT = H / BK;   // 448

    // preload tile 0
    {
        float4 a0 = *reinterpret_cast<const float4*>(Ab + 0);
        float4 a1 = *reinterpret_cast<const float4*>(Ab + 4);
        float4 b0 = *reinterpret_cast<const float4*>(Bb + 0);
        float4 b1 = *reinterpret_cast<const float4*>(Bb + 4);
        float* dA = sAs;
        float* dB = sBs;
        dA[(lcol + 0) * TROW + lrow] = a0.x; dA[(lcol + 1) * TROW + lrow] = a0.y;
        dA[(lcol + 2) * TROW + lrow] = a0.z; dA[(lcol + 3) * TROW + lrow] = a0.w;
        dA[(lcol + 4) * TROW + lrow] = a1.x; dA[(lcol + 5) * TROW + lrow] = a1.y;
        dA[(lcol + 6) * TROW + lrow] = a1.z; dA[(lcol + 7) * TROW + lrow] = a1.w;
        dB[(lcol + 0) * TROW + lrow] = b0.x; dB[(lcol + 1) * TROW + lrow] = b0.y;
        dB[(lcol + 2) * TROW + lrow] = b0.z; dB[(lcol + 3) * TROW + lrow] = b0.w;
        dB[(lcol + 4) * TROW + lrow] = b1.x; dB[(lcol + 5) * TROW + lrow] = b1.y;
        dB[(lcol + 6) * TROW + lrow] = b1.z; dB[(lcol + 7) * TROW + lrow] = b1.w;
    }
    __syncthreads();

    int kcum = 0;
    for (int it = 0; it < NIT; it++) {
        const int buf = it & 1;
        const bool has_next = (it + 1) < NIT;

        float4 pa0, pa1, pb0, pb1;
        if (has_next) {
            const float* an = Ab + (size_t)(it + 1) * BK;
            const float* bn = Bb + (size_t)(it + 1) * BK;
            pa0 = *reinterpret_cast<const float4*>(an + 0);
            pa1 = *reinterpret_cast<const float4*>(an + 4);
            pb0 = *reinterpret_cast<const float4*>(bn + 0);
            pb1 = *reinterpret_cast<const float4*>(bn + 4);
        }

        const float* As = sAs + buf * TILE_F;
        const float* Bs = sBs + buf * TILE_F;

        #pragma unroll
        for (int half = 0; half < 2; half++) {
            #pragma unroll
            for (int kk = 0; kk < 8; kk++) {
                const int k = half * 8 + kk;
                // B pairs straight from 16B smem loads
                ulonglong2 bp0 = *reinterpret_cast<const ulonglong2*>(Bs + k * TROW + tx * 8);
                ulonglong2 bp1 = *reinterpret_cast<const ulonglong2*>(Bs + k * TROW + tx * 8 + 4);
                unsigned long long bq[4] = {bp0.x, bp0.y, bp1.x, bp1.y};
                // A values; hoist ALL splats ahead of the FMA block
                float4 a0 = *reinterpret_cast<const float4*>(As + k * TROW + ty * 8);
                float4 a1 = *reinterpret_cast<const float4*>(As + k * TROW + ty * 8 + 4);
                float av[8] = {a0.x, a0.y, a0.z, a0.w, a1.x, a1.y, a1.z, a1.w};
                unsigned long long ap[8];
                #pragma unroll
                for (int i = 0; i < 8; i++) SPLAT2(ap[i], av[i]);
                // jp-outer / i-inner: bq[jp] bit-stable in slot b across 8
                // consecutive FFMA2s -> reuse-cache friendly.
                #pragma unroll
                for (int jp = 0; jp < 4; jp++)
                    #pragma unroll
                    for (int i = 0; i < 8; i++)
                        FMA2(acc[i][jp], ap[i], bq[jp]);
            }
            kcum += 8;
            if (kcum % KC == 0) {   // Eigen panel fold: per-lane rn add
                #pragma unroll
                for (int i = 0; i < 8; i++)
                    #pragma unroll
                    for (int jp = 0; jp < 4; jp++) {
                        int idx = (i * 4 + jp) * 256 + tid;
                        unsigned long long tot = sTot[idx];
                        ADD2(tot, tot, acc[i][jp]);
                        sTot[idx] = tot;
                        acc[i][jp] = 0ull;
                    }
            }
        }

        if (has_next) {
            float* dA = sAs + (buf ^ 1) * TILE_F;
            float* dB = sBs + (buf ^ 1) * TILE_F;
            dA[(lcol + 0) * TROW + lrow] = pa0.x; dA[(lcol + 1) * TROW + lrow] = pa0.y;
            dA[(lcol + 2) * TROW + lrow] = pa0.z; dA[(lcol + 3) * TROW + lrow] = pa0.w;
            dA[(lcol + 4) * TROW + lrow] = pa1.x; dA[(lcol + 5) * TROW + lrow] = pa1.y;
            dA[(lcol + 6) * TROW + lrow] = pa1.z; dA[(lcol + 7) * TROW + lrow] = pa1.w;
            dB[(lcol + 0) * TROW + lrow] = pb0.x; dB[(lcol + 1) * TROW + lrow] = pb0.y;
            dB[(lcol + 2) * TROW + lrow] = pb0.z; dB[(lcol + 3) * TROW + lrow] = pb0.w;
            dB[(lcol + 4) * TROW + lrow] = pb1.x; dB[(lcol + 5) * TROW + lrow] = pb1.y;
            dB[(lcol + 6) * TROW + lrow] = pb1.z; dB[(lcol + 7) * TROW + lrow] = pb1.w;
        }
        __syncthreads();
    }

    // remainder panel (224 k)
    #pragma unroll
    for (int i = 0; i < 8; i++)
        #pragma unroll
        for (int jp = 0; jp < 4; jp++) {
            int idx = (i * 4 + jp) * 256 + tid;
            unsigned long long tot = sTot[idx];
            ADD2(tot, tot, acc[i][jp]);
            sTot[idx] = tot;
        }

    // writeout
    #pragma unroll
    for (int i = 0; i < 8; i++) {
        int row = tile_m + ty * 8 + i;
        #pragma unroll
        for (int jp = 0; jp < 4; jp++) {
            float lo, hi;
            UNPK2(lo, hi, sTot[(i * 4 + jp) * 256 + tid]);
            C[(size_t)row * E + tile_n + tx * 8 + 2 * jp + 0] = lo;
            C[(size_t)row * E + tile_n + tx * 8 + 2 * jp + 1] = hi;
        }
    }
}

// ---------------------------------------------------------------------------
// XLA:CPU fused-loop sigmoid (FROZEN): 1/(1+exp(-x)), exp via VF32Exp with
// fused n = floor(fma(x, log2e, 0.5)).
// ---------------------------------------------------------------------------
__device__ __forceinline__ float vf32_exp(float x) {
    x = fminf(fmaxf(x, -87.8f), 88.8f);
    float fx = floorf(__fmaf_rn(x, 1.44269504088896341f, 0.5f));
    float tmp = __fmul_rn(fx, 0.693359375f);
    float z   = __fmul_rn(fx, -2.12194440e-4f);
    float r = __fsub_rn(__fsub_rn(x, tmp), z);
    float r2 = __fmul_rn(r, r);
    float y = 1.9875691500e-4f;
    y = __fmaf_rn(y, r, 1.3981999507e-3f);
    y = __fmaf_rn(y, r, 8.3334519073e-3f);
    y = __fmaf_rn(y, r, 4.1665795894e-2f);
    y = __fmaf_rn(y, r, 1.6666665459e-1f);
    y = __fmaf_rn(y, r, 5.0000001201e-1f);
    y = __fmaf_rn(y, r2, r);
    y = __fadd_rn(y, 1.0f);
    int n = (int)fx;
    return __fmul_rn(y, __int_as_float((n + 127) << 23));
}

__device__ __forceinline__ float xla_cpu_sigmoid(float x) {
    float e = vf32_exp(-x);
    return __fdiv_rn(1.0f, __fadd_rn(1.0f, e));
}

// ---------------------------------------------------------------------------
// Kernel 2: routing. One block (256 threads) per token. (FROZEN semantics)
// ---------------------------------------------------------------------------
__global__ __launch_bounds__(256) void router_topk(
    const float* __restrict__ logits,
    const float* __restrict__ bias,
    float* __restrict__ out_idx,
    float* __restrict__ out_w)
{
    __shared__ float s_score[NEXP];
    __shared__ float s_masked[NEXP];
    __shared__ float s_gscore[NGROUP];
    __shared__ int   s_gmask[NGROUP];
    __shared__ int   s_sel[TOPKN];

    const int t = blockIdx.x;
    const int e = threadIdx.x;
    const int warp = e >> 5, lane = e & 31;

    float logit = logits[(size_t)t * NEXP + e];
    float score = xla_cpu_sigmoid(logit);
    float corr = __fadd_rn(score, bias[e]);
    s_score[e] = score;

    float m1 = corr;
    #pragma unroll
    for (int o = 16; o > 0; o >>= 1)
        m1 = fmaxf(m1, __shfl_xor_sync(0xffffffffu, m1, o));
    unsigned ball = __ballot_sync(0xffffffffu, corr == m1);
    int firstlane = __ffs(ball) - 1;
    float v2 = (lane == firstlane) ? -INFINITY : corr;
    float m2 = v2;
    #pragma unroll
    for (int o = 16; o > 0; o >>= 1)
        m2 = fmaxf(m2, __shfl_xor_sync(0xffffffffu, m2, o));
    if (lane == 0) s_gscore[warp] = __fadd_rn(m1, m2);
    __syncthreads();

    if (e == 0) {
        bool used[NGROUP];
        #pragma unroll
        for (int g = 0; g < NGROUP; g++) used[g] = false;
        for (int it = 0; it < TOPKG; it++) {
            float best = -INFINITY; int bi = 0;
            for (int g = 0; g < NGROUP; g++)
                if (!used[g] && s_gscore[g] > best) { best = s_gscore[g]; bi = g; }
            used[bi] = true;
        }
        #pragma unroll
        for (int g = 0; g < NGROUP; g++) s_gmask[g] = used[g] ? 1 : 0;
    }
    __syncthreads();

    s_masked[e] = s_gmask[warp] ? corr : 0.0f;
    __syncthreads();

    if (warp == 0) {
        float lv[8];
        #pragma unroll
        for (int i = 0; i < 8; i++) lv[i] = s_masked[lane + i * 32];

        for (int it = 0; it < TOPKN; it++) {
            float best = -INFINITY; int bslot = 0;
            #pragma unroll
            for (int i = 0; i < 8; i++)
                if (lv[i] > best) { best = lv[i]; bslot = i; }
            int bidx = bslot * 32 + lane;
            #pragma unroll
            for (int o = 16; o > 0; o >>= 1) {
                float ov = __shfl_xor_sync(0xffffffffu, best, o);
                int   oi = __shfl_xor_sync(0xffffffffu, bidx, o);
                if (ov > best || (ov == best && oi < bidx)) { best = ov; bidx = oi; }
            }
            if (lane == 0) s_sel[it] = bidx;
            if (lane == (bidx & 31)) lv[bidx >> 5] = -INFINITY;
        }
        __syncwarp();

        float w = 0.0f;
        int myidx = 0;
        if (lane < TOPKN) {
            myidx = s_sel[lane];
            w = s_score[myidx];
        }
        float ws = w;
        #pragma unroll
        for (int o = 16; o > 0; o >>= 1)
            ws += __shfl_xor_sync(0xffffffffu, ws, o);
        if (lane < TOPKN) {
            float wn = __fmul_rn(__fdiv_rn(w, __fadd_rn(ws, 1e-20f)), 2.5f);
            out_idx[(size_t)t * TOPKN + lane] = (float)myidx;
            out_w[(size_t)t * TOPKN + lane] = wn;
        }
    }
}

// ---------------------------------------------------------------------------
extern "C" void kernel_launch(void* const* d_in, const int* in_sizes, int n_in,
                              void* d_out, int out_size) {
    const float* hidden = (const float*)d_in[0];
    const float* weight = (const float*)d_in[1];
    const float* bias   = (const float*)d_in[2];

    int E = in_sizes[2];
    int H = in_sizes[1] / E;
    int T = in_sizes[0] / H;

    float* logits = nullptr;
    cudaGetSymbolAddress((void**)&logits, g_logits);

    cudaFuncSetAttribute(router_gemm,
                         cudaFuncAttributeMaxDynamicSharedMemorySize, SM_TOTAL);

    dim3 gemm_grid(E / BN, T / BM);
    router_gemm<<<gemm_grid, 256, SM_TOTAL>>>(hidden, weight, logits, T, H, E);

    float* out = (float*)d_out;
    router_topk<<<T, 256>>>(logits, bias, out, out + (size_t)T * TOPKN);
}

// round 14
// speedup vs baseline: 1.7257x; 1.7257x over previous
#include <cuda_runtime.h>
#include <math.h>

#define TOKENS   16384
#define NEXP     256
#define HID      7168
#define NGROUP   8
#define TOPKG    4
#define TOPKN    8

#define KC      248          // Eigen kc panel
#define NPANEL  29           // 28 full panels + 224 remainder
#define LASTK   224

// Per-panel partial sums: part[p][t*E+e]. 29 * 16M floats = 487 MB.
__device__ float g_part[NPANEL][TOKENS * NEXP];

// ---------------------------------------------------------------------------
// Kernel 1: panel GEMM. FROZEN NUMERICS: each output of panel p is ONE serial
// ascending-k fma chain over its kc slice (lanes of fma.rn.f32x2 are
// independent rn-FMAs). Panels folded later in ascending order by router_topk.
// Grid (E/BN, T/BM, NPANEL) = (2, 128, 29) = 7424 blocks -> ~25 full waves.
// BM=BN=128, BK=8 double-buffered, 256 threads, 8x8 outputs/thread (FFMA2
// over column pairs, R11 i-outer schedule).
// ---------------------------------------------------------------------------
#define BM 128
#define BN 128
#define BK 8
#define TPAD 4
#define TROW (BM + TPAD)     // 132
#define TILE_F (BK * TROW)   // 1056 floats

#define FMA2(acc, a, b) \
    asm("fma.rn.f32x2 %0, %1, %2, %0;" : "+l"(acc) : "l"(a), "l"(b))
#define SPLAT2(p, f) \
    asm("mov.b64 %0, {%1, %1};" : "=l"(p) : "f"(f))

__global__ __launch_bounds__(256, 2) void router_gemm_panel(
    const float* __restrict__ A,   // [T, H]
    const float* __restrict__ B,   // [E, H]
    int T, int H, int E)
{
    __shared__ float sAs[2][TILE_F];
    __shared__ float sBs[2][TILE_F];

    const int tid = threadIdx.x;
    const int tx = tid & 15;
    const int ty = tid >> 4;
    const int tile_m = blockIdx.y * BM;
    const int tile_n = blockIdx.x * BN;
    const int p = blockIdx.z;
    const int kbase = p * KC;
    const int iters = (p == NPANEL - 1) ? (LASTK / BK) : (KC / BK); // 28 or 31

    // loader: 256 threads cover 128 rows x 8 cols (one float4 each)
    const int lrow = tid >> 1;
    const int lcol = (tid & 1) * 4;

    const float* Ab = A + (size_t)(tile_m + lrow) * H + kbase + lcol;
    const float* Bb = B + (size_t)(tile_n + lrow) * H + kbase + lcol;

    // acc[i][jp] = packed pair (col 2jp, 2jp+1) of row i
    unsigned long long acc[8][4];
    #pragma unroll
    for (int i = 0; i < 8; i++)
        #pragma unroll
        for (int jp = 0; jp < 4; jp++) acc[i][jp] = 0ull;

    // preload tile 0
    {
        float4 a = *reinterpret_cast<const float4*>(Ab);
        float4 b = *reinterpret_cast<const float4*>(Bb);
        sAs[0][(lcol + 0) * TROW + lrow] = a.x;
        sAs[0][(lcol + 1) * TROW + lrow] = a.y;
        sAs[0][(lcol + 2) * TROW + lrow] = a.z;
        sAs[0][(lcol + 3) * TROW + lrow] = a.w;
        sBs[0][(lcol + 0) * TROW + lrow] = b.x;
        sBs[0][(lcol + 1) * TROW + lrow] = b.y;
        sBs[0][(lcol + 2) * TROW + lrow] = b.z;
        sBs[0][(lcol + 3) * TROW + lrow] = b.w;
    }
    __syncthreads();

    for (int it = 0; it < iters; it++) {
        const int buf = it & 1;
        const bool has_next = (it + 1) < iters;

        float4 pa, pb;
        if (has_next) {
            pa = *reinterpret_cast<const float4*>(Ab + (size_t)(it + 1) * BK);
            pb = *reinterpret_cast<const float4*>(Bb + (size_t)(it + 1) * BK);
        }

        const float* As = sAs[buf];
        const float* Bs = sBs[buf];

        #pragma unroll
        for (int k = 0; k < BK; k++) {
            ulonglong2 bp0 = *reinterpret_cast<const ulonglong2*>(Bs + k * TROW + tx * 8);
            ulonglong2 bp1 = *reinterpret_cast<const ulonglong2*>(Bs + k * TROW + tx * 8 + 4);
            unsigned long long bq[4] = {bp0.x, bp0.y, bp1.x, bp1.y};
            float4 a0 = *reinterpret_cast<const float4*>(As + k * TROW + ty * 8);
            float4 a1 = *reinterpret_cast<const float4*>(As + k * TROW + ty * 8 + 4);
            float av[8] = {a0.x, a0.y, a0.z, a0.w, a1.x, a1.y, a1.z, a1.w};
            #pragma unroll
            for (int i = 0; i < 8; i++) {
                unsigned long long ap;
                SPLAT2(ap, av[i]);
                FMA2(acc[i][0], ap, bq[0]);
                FMA2(acc[i][1], ap, bq[1]);
                FMA2(acc[i][2], ap, bq[2]);
                FMA2(acc[i][3], ap, bq[3]);
            }
        }

        if (has_next) {
            float* dA = sAs[buf ^ 1];
            float* dB = sBs[buf ^ 1];
            dA[(lcol + 0) * TROW + lrow] = pa.x;
            dA[(lcol + 1) * TROW + lrow] = pa.y;
            dA[(lcol + 2) * TROW + lrow] = pa.z;
            dA[(lcol + 3) * TROW + lrow] = pa.w;
            dB[(lcol + 0) * TROW + lrow] = pb.x;
            dB[(lcol + 1) * TROW + lrow] = pb.y;
            dB[(lcol + 2) * TROW + lrow] = pb.z;
            dB[(lcol + 3) * TROW + lrow] = pb.w;
        }
        __syncthreads();
    }

    // write panel partials (u64 store = {lo=col even, hi=col odd})
    float* part = g_part[p];
    #pragma unroll
    for (int i = 0; i < 8; i++) {
        int row = tile_m + ty * 8 + i;
        float* base = part + (size_t)row * E + tile_n + tx * 8;
        #pragma unroll
        for (int jp = 0; jp < 4; jp++)
            *reinterpret_cast<unsigned long long*>(base + 2 * jp) = acc[i][jp];
    }
}

// ---------------------------------------------------------------------------
// XLA:CPU fused-loop sigmoid (FROZEN): 1/(1+exp(-x)), exp via VF32Exp with
// fused n = floor(fma(x, log2e, 0.5)).
// ---------------------------------------------------------------------------
__device__ __forceinline__ float vf32_exp(float x) {
    x = fminf(fmaxf(x, -87.8f), 88.8f);
    float fx = floorf(__fmaf_rn(x, 1.44269504088896341f, 0.5f));
    float tmp = __fmul_rn(fx, 0.693359375f);
    float z   = __fmul_rn(fx, -2.12194440e-4f);
    float r = __fsub_rn(__fsub_rn(x, tmp), z);
    float r2 = __fmul_rn(r, r);
    float y = 1.9875691500e-4f;
    y = __fmaf_rn(y, r, 1.3981999507e-3f);
    y = __fmaf_rn(y, r, 8.3334519073e-3f);
    y = __fmaf_rn(y, r, 4.1665795894e-2f);
    y = __fmaf_rn(y, r, 1.6666665459e-1f);
    y = __fmaf_rn(y, r, 5.0000001201e-1f);
    y = __fmaf_rn(y, r2, r);
    y = __fadd_rn(y, 1.0f);
    int n = (int)fx;
    return __fmul_rn(y, __int_as_float((n + 127) << 23));
}

__device__ __forceinline__ float xla_cpu_sigmoid(float x) {
    float e = vf32_exp(-x);
    return __fdiv_rn(1.0f, __fadd_rn(1.0f, e));
}

// ---------------------------------------------------------------------------
// Kernel 2: fold panels (ascending p, rn adds — Eigen order) + routing.
// One block (256 threads) per token. (FROZEN semantics)
// ---------------------------------------------------------------------------
__global__ __launch_bounds__(256) void router_topk(
    const float* __restrict__ bias,
    float* __restrict__ out_idx,
    float* __restrict__ out_w)
{
    __shared__ float s_score[NEXP];
    __shared__ float s_masked[NEXP];
    __shared__ float s_gscore[NGROUP];
    __shared__ int   s_gmask[NGROUP];
    __shared__ int   s_sel[TOPKN];

    const int t = blockIdx.x;
    const int e = threadIdx.x;
    const int warp = e >> 5, lane = e & 31;

    // fold partials: MLP-29 gather, then exact ascending rn-fold
    float v[NPANEL];
    #pragma unroll
    for (int p = 0; p < NPANEL; p++)
        v[p] = g_part[p][(size_t)t * NEXP + e];
    float logit = 0.0f;
    #pragma unroll
    for (int p = 0; p < NPANEL; p++)
        logit = __fadd_rn(logit, v[p]);

    float score = xla_cpu_sigmoid(logit);
    float corr = __fadd_rn(score, bias[e]);
    s_score[e] = score;

    float m1 = corr;
    #pragma unroll
    for (int o = 16; o > 0; o >>= 1)
        m1 = fmaxf(m1, __shfl_xor_sync(0xffffffffu, m1, o));
    unsigned ball = __ballot_sync(0xffffffffu, corr == m1);
    int firstlane = __ffs(ball) - 1;
    float v2 = (lane == firstlane) ? -INFINITY : corr;
    float m2 = v2;
    #pragma unroll
    for (int o = 16; o > 0; o >>= 1)
        m2 = fmaxf(m2, __shfl_xor_sync(0xffffffffu, m2, o));
    if (lane == 0) s_gscore[warp] = __fadd_rn(m1, m2);
    __syncthreads();

    if (e == 0) {
        bool used[NGROUP];
        #pragma unroll
        for (int g = 0; g < NGROUP; g++) used[g] = false;
        for (int it = 0; it < TOPKG; it++) {
            float best = -INFINITY; int bi = 0;
            for (int g = 0; g < NGROUP; g++)
                if (!used[g] && s_gscore[g] > best) { best = s_gscore[g]; bi = g; }
            used[bi] = true;
        }
        #pragma unroll
        for (int g = 0; g < NGROUP; g++) s_gmask[g] = used[g] ? 1 : 0;
    }
    __syncthreads();

    s_masked[e] = s_gmask[warp] ? corr : 0.0f;
    __syncthreads();

    if (warp == 0) {
        float lv[8];
        #pragma unroll
        for (int i = 0; i < 8; i++) lv[i] = s_masked[lane + i * 32];

        for (int it = 0; it < TOPKN; it++) {
            float best = -INFINITY; int bslot = 0;
            #pragma unroll
            for (int i = 0; i < 8; i++)
                if (lv[i] > best) { best = lv[i]; bslot = i; }
            int bidx = bslot * 32 + lane;
            #pragma unroll
            for (int o = 16; o > 0; o >>= 1) {
                float ov = __shfl_xor_sync(0xffffffffu, best, o);
                int   oi = __shfl_xor_sync(0xffffffffu, bidx, o);
                if (ov > best || (ov == best && oi < bidx)) { best = ov; bidx = oi; }
            }
            if (lane == 0) s_sel[it] = bidx;
            if (lane == (bidx & 31)) lv[bidx >> 5] = -INFINITY;
        }
        __syncwarp();

        float w = 0.0f;
        int myidx = 0;
        if (lane < TOPKN) {
            myidx = s_sel[lane];
            w = s_score[myidx];
        }
        float ws = w;
        #pragma unroll
        for (int o = 16; o > 0; o >>= 1)
            ws += __shfl_xor_sync(0xffffffffu, ws, o);
        if (lane < TOPKN) {
            float wn = __fmul_rn(__fdiv_rn(w, __fadd_rn(ws, 1e-20f)), 2.5f);
            out_idx[(size_t)t * TOPKN + lane] = (float)myidx;
            out_w[(size_t)t * TOPKN + lane] = wn;
        }
    }
}

// ---------------------------------------------------------------------------
extern "C" void kernel_launch(void* const* d_in, const int* in_sizes, int n_in,
                              void* d_out, int out_size) {
    const float* hidden = (const float*)d_in[0];
    const float* weight = (const float*)d_in[1];
    const float* bias   = (const float*)d_in[2];

    int E = in_sizes[2];
    int H = in_sizes[1] / E;
    int T = in_sizes[0] / H;

    dim3 gemm_grid(E / BN, T / BM, NPANEL);
    router_gemm_panel<<<gemm_grid, 256>>>(hidden, weight, T, H, E);

    float* out = (float*)d_out;
    router_topk<<<T, 256>>>(bias, out, out + (size_t)T * TOPKN);
}

// round 15
// speedup vs baseline: 1.7497x; 1.0139x over previous
#include <cuda_runtime.h>
#include <math.h>

#define TOKENS   16384
#define NEXP     256
#define HID      7168
#define NGROUP   8
#define TOPKG    4
#define TOPKN    8

#define KC      248          // Eigen kc panel
#define NPANEL  29           // 28 full panels (248) + remainder (224)

// Per-panel partial sums: part[p][t*E+e]. 29 * 16M floats = 487 MB.
__device__ float g_part[NPANEL][TOKENS * NEXP];

// ---------------------------------------------------------------------------
// Kernel 1: panel GEMM. FROZEN NUMERICS: each output of panel p is ONE serial
// ascending-k fma chain over its kc slice (fma.rn.f32x2 lanes = independent
// rn-FMAs). Panels folded in ascending order by router_topk (Eigen order).
// R15 change: BK=16 double-buffered (15 full iters + 8-k tail per 248-panel;
// last panel = 14 full iters) -> syncs per panel 31 -> 16.
// BM=BN=128, 256 threads, 8x8 outputs/thread, FFMA2 over column pairs.
// ---------------------------------------------------------------------------
#define BM 128
#define BN 128
#define BK 16
#define TPAD 4
#define TROW (BM + TPAD)     // 132
#define TILE_F (BK * TROW)   // 2112 floats

#define FMA2(acc, a, b) \
    asm("fma.rn.f32x2 %0, %1, %2, %0;" : "+l"(acc) : "l"(a), "l"(b))
#define SPLAT2(p, f) \
    asm("mov.b64 %0, {%1, %1};" : "=l"(p) : "f"(f))

__global__ __launch_bounds__(256, 2) void router_gemm_panel(
    const float* __restrict__ A,   // [T, H]
    const float* __restrict__ B,   // [E, H]
    int T, int H, int E)
{
    __shared__ float sAs[2][TILE_F];
    __shared__ float sBs[2][TILE_F];

    const int tid = threadIdx.x;
    const int tx = tid & 15;
    const int ty = tid >> 4;
    const int tile_m = blockIdx.y * BM;
    const int tile_n = blockIdx.x * BN;
    const int p = blockIdx.z;
    const int kbase = p * KC;
    const bool last_panel = (p == NPANEL - 1);
    const int nfull = last_panel ? 14 : 15;   // full BK=16 iterations
    const bool has_tail = !last_panel;        // 8-k tail for 248-panels

    // loader: 256 threads cover 128 rows x 16 cols (2 float4 each)
    const int lrow = tid >> 1;
    const int lcol = (tid & 1) * 8;

    const float* Ab = A + (size_t)(tile_m + lrow) * H + kbase + lcol;
    const float* Bb = B + (size_t)(tile_n + lrow) * H + kbase + lcol;

    // acc[i][jp] = packed pair (col 2jp, 2jp+1) of row i
    unsigned long long acc[8][4];
    #pragma unroll
    for (int i = 0; i < 8; i++)
        #pragma unroll
        for (int jp = 0; jp < 4; jp++) acc[i][jp] = 0ull;

    // preload tile 0 (16 cols)
    {
        float4 a0 = *reinterpret_cast<const float4*>(Ab + 0);
        float4 a1 = *reinterpret_cast<const float4*>(Ab + 4);
        float4 b0 = *reinterpret_cast<const float4*>(Bb + 0);
        float4 b1 = *reinterpret_cast<const float4*>(Bb + 4);
        float* dA = sAs[0];
        float* dB = sBs[0];
        dA[(lcol + 0) * TROW + lrow] = a0.x; dA[(lcol + 1) * TROW + lrow] = a0.y;
        dA[(lcol + 2) * TROW + lrow] = a0.z; dA[(lcol + 3) * TROW + lrow] = a0.w;
        dA[(lcol + 4) * TROW + lrow] = a1.x; dA[(lcol + 5) * TROW + lrow] = a1.y;
        dA[(lcol + 6) * TROW + lrow] = a1.z; dA[(lcol + 7) * TROW + lrow] = a1.w;
        dB[(lcol + 0) * TROW + lrow] = b0.x; dB[(lcol + 1) * TROW + lrow] = b0.y;
        dB[(lcol + 2) * TROW + lrow] = b0.z; dB[(lcol + 3) * TROW + lrow] = b0.w;
        dB[(lcol + 4) * TROW + lrow] = b1.x; dB[(lcol + 5) * TROW + lrow] = b1.y;
        dB[(lcol + 6) * TROW + lrow] = b1.z; dB[(lcol + 7) * TROW + lrow] = b1.w;
    }
    __syncthreads();

    const int niters = nfull + (has_tail ? 1 : 0);

    for (int it = 0; it < nfull; it++) {
        const int buf = it & 1;
        const bool has_next = (it + 1) < niters;

        // prefetch next tile (always 16 cols; bounds-safe: max col 7167)
        float4 pa0, pa1, pb0, pb1;
        if (has_next) {
            const float* an = Ab + (size_t)(it + 1) * BK;
            const float* bn = Bb + (size_t)(it + 1) * BK;
            pa0 = *reinterpret_cast<const float4*>(an + 0);
            pa1 = *reinterpret_cast<const float4*>(an + 4);
            pb0 = *reinterpret_cast<const float4*>(bn + 0);
            pb1 = *reinterpret_cast<const float4*>(bn + 4);
        }

        const float* As = sAs[buf];
        const float* Bs = sBs[buf];

        #pragma unroll
        for (int k = 0; k < BK; k++) {
            ulonglong2 bp0 = *reinterpret_cast<const ulonglong2*>(Bs + k * TROW + tx * 8);
            ulonglong2 bp1 = *reinterpret_cast<const ulonglong2*>(Bs + k * TROW + tx * 8 + 4);
            unsigned long long bq[4] = {bp0.x, bp0.y, bp1.x, bp1.y};
            float4 a0 = *reinterpret_cast<const float4*>(As + k * TROW + ty * 8);
            float4 a1 = *reinterpret_cast<const float4*>(As + k * TROW + ty * 8 + 4);
            float av[8] = {a0.x, a0.y, a0.z, a0.w, a1.x, a1.y, a1.z, a1.w};
            #pragma unroll
            for (int i = 0; i < 8; i++) {
                unsigned long long ap;
                SPLAT2(ap, av[i]);
                FMA2(acc[i][0], ap, bq[0]);
                FMA2(acc[i][1], ap, bq[1]);
                FMA2(acc[i][2], ap, bq[2]);
                FMA2(acc[i][3], ap, bq[3]);
            }
        }

        if (has_next) {
            float* dA = sAs[buf ^ 1];
            float* dB = sBs[buf ^ 1];
            dA[(lcol + 0) * TROW + lrow] = pa0.x; dA[(lcol + 1) * TROW + lrow] = pa0.y;
            dA[(lcol + 2) * TROW + lrow] = pa0.z; dA[(lcol + 3) * TROW + lrow] = pa0.w;
            dA[(lcol + 4) * TROW + lrow] = pa1.x; dA[(lcol + 5) * TROW + lrow] = pa1.y;
            dA[(lcol + 6) * TROW + lrow] = pa1.z; dA[(lcol + 7) * TROW + lrow] = pa1.w;
            dB[(lcol + 0) * TROW + lrow] = pb0.x; dB[(lcol + 1) * TROW + lrow] = pb0.y;
            dB[(lcol + 2) * TROW + lrow] = pb0.z; dB[(lcol + 3) * TROW + lrow] = pb0.w;
            dB[(lcol + 4) * TROW + lrow] = pb1.x; dB[(lcol + 5) * TROW + lrow] = pb1.y;
            dB[(lcol + 6) * TROW + lrow] = pb1.z; dB[(lcol + 7) * TROW + lrow] = pb1.w;
        }
        __syncthreads();
    }

    // 8-k tail (k = 240..247 of a 248-panel), buffer nfull&1
    if (has_tail) {
        const float* As = sAs[nfull & 1];
        const float* Bs = sBs[nfull & 1];
        #pragma unroll
        for (int k = 0; k < 8; k++) {
            ulonglong2 bp0 = *reinterpret_cast<const ulonglong2*>(Bs + k * TROW + tx * 8);
            ulonglong2 bp1 = *reinterpret_cast<const ulonglong2*>(Bs + k * TROW + tx * 8 + 4);
            unsigned long long bq[4] = {bp0.x, bp0.y, bp1.x, bp1.y};
            float4 a0 = *reinterpret_cast<const float4*>(As + k * TROW + ty * 8);
            float4 a1 = *reinterpret_cast<const float4*>(As + k * TROW + ty * 8 + 4);
            float av[8] = {a0.x, a0.y, a0.z, a0.w, a1.x, a1.y, a1.z, a1.w};
            #pragma unroll
            for (int i = 0; i < 8; i++) {
                unsigned long long ap;
                SPLAT2(ap, av[i]);
                FMA2(acc[i][0], ap, bq[0]);
                FMA2(acc[i][1], ap, bq[1]);
                FMA2(acc[i][2], ap, bq[2]);
                FMA2(acc[i][3], ap, bq[3]);
            }
        }
    }

    // write panel partials (u64 store = {lo=col even, hi=col odd})
    float* part = g_part[p];
    #pragma unroll
    for (int i = 0; i < 8; i++) {
        int row = tile_m + ty * 8 + i;
        float* base = part + (size_t)row * E + tile_n + tx * 8;
        #pragma unroll
        for (int jp = 0; jp < 4; jp++)
            *reinterpret_cast<unsigned long long*>(base + 2 * jp) = acc[i][jp];
    }
}

// ---------------------------------------------------------------------------
// XLA:CPU fused-loop sigmoid (FROZEN): 1/(1+exp(-x)), exp via VF32Exp with
// fused n = floor(fma(x, log2e, 0.5)).
// ---------------------------------------------------------------------------
__device__ __forceinline__ float vf32_exp(float x) {
    x = fminf(fmaxf(x, -87.8f), 88.8f);
    float fx = floorf(__fmaf_rn(x, 1.44269504088896341f, 0.5f));
    float tmp = __fmul_rn(fx, 0.693359375f);
    float z   = __fmul_rn(fx, -2.12194440e-4f);
    float r = __fsub_rn(__fsub_rn(x, tmp), z);
    float r2 = __fmul_rn(r, r);
    float y = 1.9875691500e-4f;
    y = __fmaf_rn(y, r, 1.3981999507e-3f);
    y = __fmaf_rn(y, r, 8.3334519073e-3f);
    y = __fmaf_rn(y, r, 4.1665795894e-2f);
    y = __fmaf_rn(y, r, 1.6666665459e-1f);
    y = __fmaf_rn(y, r, 5.0000001201e-1f);
    y = __fmaf_rn(y, r2, r);
    y = __fadd_rn(y, 1.0f);
    int n = (int)fx;
    return __fmul_rn(y, __int_as_float((n + 127) << 23));
}

__device__ __forceinline__ float xla_cpu_sigmoid(float x) {
    float e = vf32_exp(-x);
    return __fdiv_rn(1.0f, __fadd_rn(1.0f, e));
}

// ---------------------------------------------------------------------------
// Kernel 2: fold panels (ascending p, rn adds — Eigen order) + routing.
// One block (256 threads) per token. (FROZEN semantics)
// ---------------------------------------------------------------------------
__global__ __launch_bounds__(256) void router_topk(
    const float* __restrict__ bias,
    float* __restrict__ out_idx,
    float* __restrict__ out_w)
{
    __shared__ float s_score[NEXP];
    __shared__ float s_masked[NEXP];
    __shared__ float s_gscore[NGROUP];
    __shared__ int   s_gmask[NGROUP];
    __shared__ int   s_sel[TOPKN];

    const int t = blockIdx.x;
    const int e = threadIdx.x;
    const int warp = e >> 5, lane = e & 31;

    // fold partials: MLP-29 gather, then exact ascending rn-fold
    float v[NPANEL];
    #pragma unroll
    for (int p = 0; p < NPANEL; p++)
        v[p] = g_part[p][(size_t)t * NEXP + e];
    float logit = 0.0f;
    #pragma unroll
    for (int p = 0; p < NPANEL; p++)
        logit = __fadd_rn(logit, v[p]);

    float score = xla_cpu_sigmoid(logit);
    float corr = __fadd_rn(score, bias[e]);
    s_score[e] = score;

    float m1 = corr;
    #pragma unroll
    for (int o = 16; o > 0; o >>= 1)
        m1 = fmaxf(m1, __shfl_xor_sync(0xffffffffu, m1, o));
    unsigned ball = __ballot_sync(0xffffffffu, corr == m1);
    int firstlane = __ffs(ball) - 1;
    float v2 = (lane == firstlane) ? -INFINITY : corr;
    float m2 = v2;
    #pragma unroll
    for (int o = 16; o > 0; o >>= 1)
        m2 = fmaxf(m2, __shfl_xor_sync(0xffffffffu, m2, o));
    if (lane == 0) s_gscore[warp] = __fadd_rn(m1, m2);
    __syncthreads();

    if (e == 0) {
        bool used[NGROUP];
        #pragma unroll
        for (int g = 0; g < NGROUP; g++) used[g] = false;
        for (int it = 0; it < TOPKG; it++) {
            float best = -INFINITY; int bi = 0;
            for (int g = 0; g < NGROUP; g++)
                if (!used[g] && s_gscore[g] > best) { best = s_gscore[g]; bi = g; }
            used[bi] = true;
        }
        #pragma unroll
        for (int g = 0; g < NGROUP; g++) s_gmask[g] = used[g] ? 1 : 0;
    }
    __syncthreads();

    s_masked[e] = s_gmask[warp] ? corr : 0.0f;
    __syncthreads();

    if (warp == 0) {
        float lv[8];
        #pragma unroll
        for (int i = 0; i < 8; i++) lv[i] = s_masked[lane + i * 32];

        for (int it = 0; it < TOPKN; it++) {
            float best = -INFINITY; int bslot = 0;
            #pragma unroll
            for (int i = 0; i < 8; i++)
                if (lv[i] > best) { best = lv[i]; bslot = i; }
            int bidx = bslot * 32 + lane;
            #pragma unroll
            for (int o = 16; o > 0; o >>= 1) {
                float ov = __shfl_xor_sync(0xffffffffu, best, o);
                int   oi = __shfl_xor_sync(0xffffffffu, bidx, o);
                if (ov > best || (ov == best && oi < bidx)) { best = ov; bidx = oi; }
            }
            if (lane == 0) s_sel[it] = bidx;
            if (lane == (bidx & 31)) lv[bidx >> 5] = -INFINITY;
        }
        __syncwarp();

        float w = 0.0f;
        int myidx = 0;
        if (lane < TOPKN) {
            myidx = s_sel[lane];
            w = s_score[myidx];
        }
        float ws = w;
        #pragma unroll
        for (int o = 16; o > 0; o >>= 1)
            ws += __shfl_xor_sync(0xffffffffu, ws, o);
        if (lane < TOPKN) {
            float wn = __fmul_rn(__fdiv_rn(w, __fadd_rn(ws, 1e-20f)), 2.5f);
            out_idx[(size_t)t * TOPKN + lane] = (float)myidx;
            out_w[(size_t)t * TOPKN + lane] = wn;
        }
    }
}

// ---------------------------------------------------------------------------
extern "C" void kernel_launch(void* const* d_in, const int* in_sizes, int n_in,
                              void* d_out, int out_size) {
    const float* hidden = (const float*)d_in[0];
    const float* weight = (const float*)d_in[1];
    const float* bias   = (const float*)d_in[2];

    int E = in_sizes[2];
    int H = in_sizes[1] / E;
    int T = in_sizes[0] / H;

    dim3 gemm_grid(E / BN, T / BM, NPANEL);
    router_gemm_panel<<<gemm_grid, 256>>>(hidden, weight, T, H, E);

    float* out = (float*)d_out;
    router_topk<<<T, 256>>>(bias, out, out + (size_t)T * TOPKN);
}